// round 5
// baseline (speedup 1.0000x reference)
#include <cuda_runtime.h>
#include <cuda_bf16.h>

#define T_DIM    2048
#define NUM_SEG  64
#define SEG      32
#define F_DIM    32
#define H_DIM    128
#define FEAT_DIM 4

#define THREADS 512            // 16 warps; 1 output row per warp
#define ROWS_PER_BLOCK 16
#define GRID (T_DIM / ROWS_PER_BLOCK)   // 128 blocks -> one per SM

// float4-based smem layouts (bank-conflict-free, verified):
//  Wq_s[ff][k4]  : W row ff as 32 float4 k-chunks, pitch 33 f4 (132 words)
//                  lane=ff LDS.128: bank start 4*ff mod 32 -> conflict-free
//  h4_s[j][k4]   : h_seg row j as 32 float4, pitch 32 f4 (no pad needed:
//                  per-lane [j][lane] access -> lane banks 4l..4l+3 distinct)
//  Wh4_s[j][ff4] : Wh row j as 8 float4 ff-chunks, pitch 9 f4 (36 words)
//                  lane=j LDS.128: bank start 4*j mod 32 -> conflict-free

__global__ __launch_bounds__(THREADS, 1)
void horizon_fused_kernel(const float* __restrict__ f,
                          const float* __restrict__ h,
                          const float* __restrict__ features,
                          const float* __restrict__ hor,
                          const float* __restrict__ W_w,
                          const float* __restrict__ W_b,
                          float* __restrict__ S)
{
    __shared__ float4 Wq_s[F_DIM][33];     // 16.5 KB
    __shared__ float4 h4_s[SEG][32];       // 16 KB
    __shared__ float4 Wh4_s[SEG][9];       // 4.5 KB

    const int tid  = threadIdx.x;
    const int blk  = blockIdx.x;
    const int seg  = blk >> 1;
    const int seg0 = seg * SEG;

    const int warp = tid >> 5;             // 0..15
    const int lane = tid & 31;

    const int i  = seg0 + (blk & 1) * ROWS_PER_BLOCK + warp;  // output row
    const int gj = seg0 + lane;                               // segment column

    // ===== Phase 0: issue all DRAM loads early (latency hidden by Wh) =====
    float4 fv[F_DIM / 4];
    {
        const float4* fp = reinterpret_cast<const float4*>(f + ((size_t)i * T_DIM + gj) * F_DIM);
        #pragma unroll
        for (int k4 = 0; k4 < F_DIM / 4; k4++) fv[k4] = fp[k4];
    }
    const size_t mb = (size_t)i * T_DIM + gj;
    const float bearing = hor[mb];
    const float dist    = features[mb * FEAT_DIM];
    const float bias    = W_b[lane];       // broadcastable, L1-cached

    // ===== Phase 1: stage h_seg and W (both coalesced, no transpose) ======
    {
        const float4* h4 = reinterpret_cast<const float4*>(h + (size_t)seg0 * H_DIM);
        const float4* w4 = reinterpret_cast<const float4*>(W_w);
        #pragma unroll
        for (int n = tid; n < SEG * (H_DIM / 4); n += THREADS) {   // 1024/512 = 2 iters
            h4_s[n >> 5][n & 31] = h4[n];
            Wq_s[n >> 5][n & 31] = w4[n];     // row ff = n>>5, chunk k4 = n&31
        }
    }
    __syncthreads();

    // ===== Phase 2: Wh[j][ff] for this segment; warp -> j in {warp, warp+16}
    // lane = ff. Per k4: 1 per-lane LDS.128 (W) + 2 broadcast LDS.128 (h) + 8 FFMA.
    {
        const int j0 = warp, j1 = warp + 16;
        float acc0 = bias, acc1 = bias;
        #pragma unroll 8
        for (int k4 = 0; k4 < H_DIM / 4; k4++) {
            const float4 w  = Wq_s[lane][k4];
            const float4 a0 = h4_s[j0][k4];
            const float4 a1 = h4_s[j1][k4];
            acc0 += a0.x * w.x + a0.y * w.y + a0.z * w.z + a0.w * w.w;
            acc1 += a1.x * w.x + a1.y * w.y + a1.z * w.z + a1.w * w.w;
        }
        // scalar stores: Wh4_s[j] row = 36 words; bank lane+4j mod 32 -> conflict-free
        reinterpret_cast<float*>(&Wh4_s[j0][0])[lane] = acc0;
        reinterpret_cast<float*>(&Wh4_s[j1][0])[lane] = acc1;
    }
    __syncthreads();

    // ===== Phase 3: logit = dot(f[i,gj,:], Wh[gj,:])  (LDS.128 per-lane) ===
    float logit = 0.f;
    #pragma unroll
    for (int k4 = 0; k4 < F_DIM / 4; k4++) {
        const float4 w = Wh4_s[lane][k4];
        const float4 a = fv[k4];
        logit += a.x * w.x + a.y * w.y + a.z * w.z + a.w * w.w;
    }

    const bool bad = (bearing < 0.f) || (dist > 10.f) || (i == gj);
    const float val = bad ? -1000.f : logit;

    // ===== Phase 4: warp softmax over the 32 in-segment entries ===========
    float m = val;
    #pragma unroll
    for (int off = 16; off; off >>= 1)
        m = fmaxf(m, __shfl_xor_sync(0xFFFFFFFFu, m, off));
    const float e = expf(val - m);
    float ssum = e;
    #pragma unroll
    for (int off = 16; off; off >>= 1)
        ssum += __shfl_xor_sync(0xFFFFFFFFu, ssum, off);
    const float attn = e / ssum;

    // ===== Phase 5: S[i,:] = sum_j attn_j * h_seg[j,:] =====================
    // lane owns 4 contiguous cols; h4_s[jj][lane] is conflict-free LDS.128.
    float4 A = make_float4(0.f, 0.f, 0.f, 0.f);
    #pragma unroll
    for (int jj = 0; jj < SEG; jj++) {
        const float a = __shfl_sync(0xFFFFFFFFu, attn, jj);
        const float4 hv = h4_s[jj][lane];
        A.x += a * hv.x;  A.y += a * hv.y;  A.z += a * hv.z;  A.w += a * hv.w;
    }

    reinterpret_cast<float4*>(S + (size_t)i * H_DIM)[lane] = A;   // STG.128
}

extern "C" void kernel_launch(void* const* d_in, const int* in_sizes, int n_in,
                              void* d_out, int out_size)
{
    // metadata order: f, h, features, hor_bearings_MTX, W_w, W_b, sub_batches
    const float* f        = (const float*)d_in[0];
    const float* h        = (const float*)d_in[1];
    const float* features = (const float*)d_in[2];
    const float* hor      = (const float*)d_in[3];
    const float* W_w      = (const float*)d_in[4];
    const float* W_b      = (const float*)d_in[5];
    float* S = (float*)d_out;

    horizon_fused_kernel<<<GRID, THREADS>>>(f, h, features, hor, W_w, W_b, S);
}

// round 6
// speedup vs baseline: 1.0030x; 1.0030x over previous
#include <cuda_runtime.h>
#include <cuda_bf16.h>

#define T_DIM    2048
#define NUM_SEG  64
#define SEG      32
#define F_DIM    32
#define H_DIM    128
#define FEAT_DIM 4

#define THREADS 512            // 16 warps; 1 output row per warp
#define ROWS_PER_BLOCK 16
#define GRID (T_DIM / ROWS_PER_BLOCK)   // 128 blocks -> one per SM

#define SP_PITCH 12            // floats per row of partial-scratch: 48B, 16B-aligned,
                               // 12*lane mod 32 hits 32 distinct banks per 8-lane phase

__global__ __launch_bounds__(THREADS, 1)
void horizon_fused_kernel(const float* __restrict__ f,
                          const float* __restrict__ h,
                          const float* __restrict__ features,
                          const float* __restrict__ hor,
                          const float* __restrict__ W_w,
                          const float* __restrict__ W_b,
                          float* __restrict__ S)
{
    __shared__ float4 Wq_s[F_DIM][33];         // 16.5 KB  W rows as float4 chunks
    __shared__ float4 h4_s[SEG][32];           // 16 KB    h_seg rows as float4
    __shared__ float4 Wh4_s[SEG][9];           // 4.5 KB   Wh rows as float4 chunks
    __shared__ float  sp[16][SEG][SP_PITCH];   // 24 KB    per-warp logit partials

    const int tid  = threadIdx.x;
    const int blk  = blockIdx.x;
    const int seg  = blk >> 1;
    const int seg0 = seg * SEG;

    const int warp = tid >> 5;                 // 0..15
    const int lane = tid & 31;

    const int i  = seg0 + (blk & 1) * ROWS_PER_BLOCK + warp;  // output row
    const int gj = seg0 + lane;                               // lane's segment column

    // ===== Phase 0: issue all DRAM loads early =============================
    // f block for row i is 4KB CONTIGUOUS: load linearly -> each LDG.128
    // covers 512B (4 lines), not 32 lines.
    float4 fv[8];
    {
        const float4* fblk = reinterpret_cast<const float4*>(
            f + ((size_t)i * T_DIM + seg0) * F_DIM);
        #pragma unroll
        for (int m = 0; m < 8; m++)
            fv[m] = fblk[m * 32 + lane];       // row 4m+lane/8, chunk lane%8
    }
    const size_t mb = (size_t)i * T_DIM + gj;
    const float bearing = hor[mb];
    const float dist    = features[mb * FEAT_DIM];
    const float bias    = W_b[lane];

    // ===== Phase 1: stage h_seg and W (coalesced) ==========================
    {
        const float4* h4 = reinterpret_cast<const float4*>(h + (size_t)seg0 * H_DIM);
        const float4* w4 = reinterpret_cast<const float4*>(W_w);
        #pragma unroll
        for (int n = tid; n < SEG * (H_DIM / 4); n += THREADS) {   // 2 iters
            h4_s[n >> 5][n & 31] = h4[n];
            Wq_s[n >> 5][n & 31] = w4[n];
        }
    }
    __syncthreads();

    // ===== Phase 2: Wh[j][ff]; warp -> rows {warp, warp+16}, lane = ff =====
    {
        const int j0 = warp, j1 = warp + 16;
        float acc0 = bias, acc1 = bias;
        #pragma unroll 8
        for (int k4 = 0; k4 < H_DIM / 4; k4++) {
            const float4 w  = Wq_s[lane][k4];      // conflict-free LDS.128
            const float4 a0 = h4_s[j0][k4];        // broadcast
            const float4 a1 = h4_s[j1][k4];        // broadcast
            acc0 += a0.x * w.x + a0.y * w.y + a0.z * w.z + a0.w * w.w;
            acc1 += a1.x * w.x + a1.y * w.y + a1.z * w.z + a1.w * w.w;
        }
        reinterpret_cast<float*>(&Wh4_s[j0][0])[lane] = acc0;  // conflict-free
        reinterpret_cast<float*>(&Wh4_s[j1][0])[lane] = acc1;
    }
    __syncthreads();

    // ===== Phase 3: partial logit dots + per-warp redistribution ===========
    // Lane l, iter m holds chunk c=l%8 of row j=4m+l/8.
    {
        float* spw = &sp[warp][0][0];
        const int g = lane >> 3;               // 0..3
        const int c = lane & 7;                // chunk 0..7
        #pragma unroll
        for (int m = 0; m < 8; m++) {
            const int j = 4 * m + g;
            const float4 w = Wh4_s[j][c];      // conflict-free per 8-lane phase
            const float4 a = fv[m];
            spw[j * SP_PITCH + c] =
                a.x * w.x + a.y * w.y + a.z * w.z + a.w * w.w;  // conflict-free STS
        }
        __syncwarp();
        // lane j sums its 8 chunks (two aligned LDS.128, conflict-free)
        const float4 A = *reinterpret_cast<const float4*>(spw + lane * SP_PITCH);
        const float4 B = *reinterpret_cast<const float4*>(spw + lane * SP_PITCH + 4);
        const float logit = (A.x + A.y + A.z + A.w) + (B.x + B.y + B.z + B.w);

        const bool bad = (bearing < 0.f) || (dist > 10.f) || (i == gj);
        const float val = bad ? -1000.f : logit;

        // ===== Phase 4: warp softmax =======================================
        float mx = val;
        #pragma unroll
        for (int off = 16; off; off >>= 1)
            mx = fmaxf(mx, __shfl_xor_sync(0xFFFFFFFFu, mx, off));
        const float e = expf(val - mx);
        float ssum = e;
        #pragma unroll
        for (int off = 16; off; off >>= 1)
            ssum += __shfl_xor_sync(0xFFFFFFFFu, ssum, off);
        const float attn = e / ssum;

        // ===== Phase 5: S[i,:] = sum_j attn_j * h_seg[j,:] =================
        float4 Acc = make_float4(0.f, 0.f, 0.f, 0.f);
        #pragma unroll
        for (int jj = 0; jj < SEG; jj++) {
            const float a = __shfl_sync(0xFFFFFFFFu, attn, jj);
            const float4 hv = h4_s[jj][lane];  // conflict-free LDS.128
            Acc.x += a * hv.x;  Acc.y += a * hv.y;
            Acc.z += a * hv.z;  Acc.w += a * hv.w;
        }
        reinterpret_cast<float4*>(S + (size_t)i * H_DIM)[lane] = Acc;  // STG.128
    }
}

extern "C" void kernel_launch(void* const* d_in, const int* in_sizes, int n_in,
                              void* d_out, int out_size)
{
    // metadata order: f, h, features, hor_bearings_MTX, W_w, W_b, sub_batches
    const float* f        = (const float*)d_in[0];
    const float* h        = (const float*)d_in[1];
    const float* features = (const float*)d_in[2];
    const float* hor      = (const float*)d_in[3];
    const float* W_w      = (const float*)d_in[4];
    const float* W_b      = (const float*)d_in[5];
    float* S = (float*)d_out;

    horizon_fused_kernel<<<GRID, THREADS>>>(f, h, features, hor, W_w, W_b, S);
}